// round 12
// baseline (speedup 1.0000x reference)
#include <cuda_runtime.h>
#include <cstdint>

// Encoding: B=64, C=512, N=784, K=32. x:(B,C,N) f32; out:(B,K,C) f32.
// K1: logits mma tf32 + softmax -> A ([b][n][k'], permuted, tf32) + wsum.
//     Paired x_s layout -> conflict-free LDS.64 fragments.
// K2: out = A^T x, 64-c blocks, double-buffered, LDS.64 A-fragments, fused epilogue.

#define CDIM 512
#define KD 32
#define NPIX 784
#define BDIM 64
#define CH1 9
#define TS 16
#define TILES1 49
#define XROW 520      // K1 x_s row stride (floats)

__device__ float g_A[(size_t)BDIM * NPIX * KD];     // 6.4 MB, [b][n][k']
__device__ float g_wsum[BDIM * CH1 * KD];

__device__ __forceinline__ float rtf32(float v) {
    asm("cvt.rna.tf32.f32 %0, %1;" : "=f"(v) : "f"(v));
    return v;
}
__device__ __forceinline__ void mma8(float* d, uint32_t a0, uint32_t a1,
                                     uint32_t a2, uint32_t a3,
                                     uint32_t b0, uint32_t b1) {
    asm volatile(
        "mma.sync.aligned.m16n8k8.row.col.f32.tf32.tf32.f32 "
        "{%0,%1,%2,%3}, {%4,%5,%6,%7}, {%8,%9}, {%0,%1,%2,%3};"
        : "+f"(d[0]), "+f"(d[1]), "+f"(d[2]), "+f"(d[3])
        : "r"(a0), "r"(a1), "r"(a2), "r"(a3), "r"(b0), "r"(b1));
}
#define BITS(f) __float_as_uint(f)

// =========================== K1: logits + softmax ===========================
__global__ __launch_bounds__(256) void enc_k1(const float* __restrict__ x,
                                              const float* __restrict__ cw,
                                              const float* __restrict__ scale) {
    const int b = blockIdx.x / CH1, ch = blockIdx.x % CH1;
    const int tile0 = ch * TILES1 / CH1, tile1 = (ch + 1) * TILES1 / CH1;
    const int t = threadIdx.x, w = t >> 5, l = t & 31;
    const int kt = w & 3, h = w >> 2;         // warp = (k-tile, c-half)

    __shared__ float x_s[TS * XROW];          // paired layout: (c, c+4) adjacent
    __shared__ float xc_s[TS * 34];
    __shared__ float red_s[4 * 32 * 4];
    __shared__ float part_s[TS * 17];
    __shared__ float csq_s[KD], scl_s[KD];
    __shared__ float wsum_s[8][KD];

    if (t < KD) scl_s[t] = __ldg(&scale[t]);
#pragma unroll
    for (int kk = 0; kk < 4; kk++) {
        int k = 4 * w + kk;
        float s = 0.f;
#pragma unroll
        for (int q = 0; q < 4; q++) {
            float4 v = __ldg((const float4*)&cw[k * CDIM + l * 16 + 4 * q]);
            float e0 = rtf32(v.x), e1 = rtf32(v.y), e2 = rtf32(v.z), e3 = rtf32(v.w);
            s += e0 * e0 + e1 * e1 + e2 * e2 + e3 * e3;
        }
#pragma unroll
        for (int o = 16; o; o >>= 1) s += __shfl_xor_sync(~0u, s, o);
        if (l == 0) csq_s[k] = s;
    }

    // persistent codeword B-fragments (tf32): warp covers k=8kt..+7, c-half h
    uint32_t cwf0[32], cwf1[32];
    const int crow = kt * 8 + (l >> 2), cp = l & 3;
#pragma unroll
    for (int s = 0; s < 32; s++) {
        int c = h * 256 + 8 * s + cp;
        cwf0[s] = BITS(rtf32(__ldg(&cw[crow * CDIM + c])));
        cwf1[s] = BITS(rtf32(__ldg(&cw[crow * CDIM + c + 4])));
    }

    float wsum_acc = 0.f;
    const float* xb = x + (size_t)b * CDIM * NPIX;
    const int nl = t & 15, cb16 = t >> 4;
    // staging slot base: (c>>3)*16 + (c&3)*2 + ((c>>2)&1), c = cb16 + 16i -> +32i
    const int st_base = nl * XROW + (cb16 >> 3) * 16 + (cb16 & 3) * 2 + ((cb16 >> 2) & 1);

    float buf[32];
#define LDREG(n0) _Pragma("unroll") \
    for (int i = 0; i < 32; i++) buf[i] = __ldg(&xb[(cb16 + 16 * i) * NPIX + (n0) + nl]);

    LDREG(tile0 * TS);
    for (int tile = tile0; tile < tile1; tile++) {
        const int n0 = tile * TS;
        __syncthreads();
        // commit prefetched tile (raw fp32; HMMA truncates) + xsq partial (exact)
        float xsqp = 0.f;
#pragma unroll
        for (int i = 0; i < 32; i++) {
            float v = buf[i];
            x_s[st_base + 32 * i] = v;
            xsqp = fmaf(v, v, xsqp);
        }
        part_s[nl * 17 + cb16] = xsqp;
        __syncthreads();
        if (tile + 1 < tile1) { LDREG(n0 + TS); }   // overlap next-tile DRAM latency

        // phase 1: xc = x . cw^T; paired layout -> 2 conflict-free LDS.64/step
        float dA[4] = {0.f, 0.f, 0.f, 0.f}, dB[4] = {0.f, 0.f, 0.f, 0.f};
        const int r0 = (l >> 2) * XROW, r1 = r0 + 8 * XROW;
        const int cp2 = (l & 3) * 2;
#pragma unroll
        for (int s = 0; s < 32; s++) {
            int off = (h * 32 + s) * 16 + cp2;
            float2 p0 = *(const float2*)&x_s[r0 + off];   // (n,c), (n,c+4)
            float2 p1 = *(const float2*)&x_s[r1 + off];   // (n+8,c), (n+8,c+4)
            mma8((s & 1) ? dB : dA,
                 BITS(p0.x), BITS(p1.x), BITS(p0.y), BITS(p1.y),
                 cwf0[s], cwf1[s]);
        }
        float d4[4];
#pragma unroll
        for (int i = 0; i < 4; i++) d4[i] = dA[i] + dB[i];
        if (h == 1)
            *(float4*)&red_s[(kt * 32 + l) * 4] = make_float4(d4[0], d4[1], d4[2], d4[3]);
        __syncthreads();
        if (h == 0) {
            float4 rr = *(const float4*)&red_s[(kt * 32 + l) * 4];
            d4[0] += rr.x; d4[1] += rr.y; d4[2] += rr.z; d4[3] += rr.w;
            int rrow = l >> 2, cc = kt * 8 + 2 * (l & 3);
            *(float2*)&xc_s[rrow * 34 + cc] = make_float2(d4[0], d4[1]);
            *(float2*)&xc_s[(rrow + 8) * 34 + cc] = make_float2(d4[2], d4[3]);
        }
        __syncthreads();

        // softmax: warp w rows {w, w+8}, lane = k; write A with k-permutation
        const int kperm = (l >> 4) * 16 + (l & 7) * 2 + ((l >> 3) & 1);
#pragma unroll
        for (int r = 0; r < 2; r++) {
            int n = w + 8 * r;
            float xs = 0.f;
#pragma unroll
            for (int q = 0; q < 16; q++) xs += part_s[n * 17 + q];
            float xc = xc_s[n * 34 + l];
            float dd = scl_s[l] * (xs - 2.f * xc + csq_s[l]);
            float m = dd;
#pragma unroll
            for (int o = 16; o; o >>= 1) m = fmaxf(m, __shfl_xor_sync(~0u, m, o));
            float e = __expf(dd - m);
            float ss = e;
#pragma unroll
            for (int o = 16; o; o >>= 1) ss += __shfl_xor_sync(~0u, ss, o);
            float a = rtf32(__fdividef(e, ss));
            wsum_acc += a;
            g_A[((size_t)b * NPIX + n0 + n) * KD + kperm] = a;   // coalesced (128B line)
        }
    }

    wsum_s[w][l] = wsum_acc;
    __syncthreads();
    if (t < KD) {
        float s = 0.f;
#pragma unroll
        for (int ww = 0; ww < 8; ww++) s += wsum_s[ww][t];
        g_wsum[(b * CH1 + ch) * KD + t] = s;
    }
}

// ==== K2: out = A^T x, 64-c blocks, double-buffered, LDS.64 A-frags, fused epilogue ====
// A_s stride 48: permuted k makes (k, k+8) adjacent -> conflict-free LDS.64.
// x_s: n-group j (=n/4) major, stride 66 float4 (round-10 proven layout).
__global__ __launch_bounds__(256) void enc_k2(const float* __restrict__ x,
                                              const float* __restrict__ cw,
                                              float* __restrict__ out) {
    const int b = blockIdx.x >> 3, cb = blockIdx.x & 7;   // cb: 64-c block
    const int t = threadIdx.x, w = t >> 5, l = t & 31;
    const int mt = w & 1, cq = w >> 1;   // warp = (k-half 16, c-quarter 16)

    __shared__ float A_s[2][32 * 48];      // [32n][32k'], stride 48
    __shared__ float x_s[2][8 * 66 * 4];   // blocked, 2112 floats/buf
    __shared__ float wsum_s[KD];

    if (t < KD) {
        float s = 0.f;
#pragma unroll
        for (int ch = 0; ch < CH1; ch++) s += g_wsum[(b * CH1 + ch) * KD + t];
        wsum_s[t] = s;
    }

    float acc[2][4];
#pragma unroll
    for (int i = 0; i < 2; i++)
#pragma unroll
        for (int j = 0; j < 4; j++) acc[i][j] = 0.f;

    const float* xb = x + ((size_t)b * CDIM + cb * 64) * NPIX;
    const float* Ab = g_A + (size_t)b * NPIX * KD;
    const int ar = t >> 3, ak4 = t & 7;   // A staging: n row, k-float4
    const int xc_ = t >> 2, xj = t & 3;   // x staging: c row, n-group (and +4)

#define K2_LDG(n0, av, v0, v1) do { \
        av = ((n0) + ar < NPIX) \
            ? __ldg((const float4*)&Ab[(size_t)((n0) + ar) * KD + 4 * ak4]) \
            : make_float4(0.f, 0.f, 0.f, 0.f); \
        v0 = ((n0) + 4 * xj < NPIX) \
            ? __ldg((const float4*)&xb[(size_t)xc_ * NPIX + (n0) + 4 * xj]) \
            : make_float4(0.f, 0.f, 0.f, 0.f); \
        v1 = ((n0) + 4 * (xj + 4) < NPIX) \
            ? __ldg((const float4*)&xb[(size_t)xc_ * NPIX + (n0) + 4 * (xj + 4)]) \
            : make_float4(0.f, 0.f, 0.f, 0.f); \
    } while (0)

#define K2_STS(bi, av, v0, v1) do { \
        *(float4*)&A_s[bi][ar * 48 + 4 * ak4] = av; \
        *(float4*)&x_s[bi][(xj * 66 + xc_) * 4] = v0; \
        *(float4*)&x_s[bi][((xj + 4) * 66 + xc_) * 4] = v1; \
    } while (0)

    {   // prologue: stage tile 0 into buffer 0
        float4 av, v0, v1;
        K2_LDG(0, av, v0, v1);
        K2_STS(0, av, v0, v1);
    }
    __syncthreads();

    const int q3 = l & 3, c7 = l >> 2;
    const int ka = mt * 16 + 2 * c7;     // permuted slot of (k0, k0+8) pair

    for (int tl = 0; tl < 25; tl++) {
        const int cur = tl & 1;
        float4 av, v0, v1;
        if (tl < 24) { K2_LDG((tl + 1) * 32, av, v0, v1); }   // overlap with mma

#pragma unroll
        for (int ks = 0; ks < 4; ks++) {
            int pn = 8 * ks + q3;
            float2 pa = *(const float2*)&A_s[cur][pn * 48 + ka];        // a0, a1
            float2 pb = *(const float2*)&A_s[cur][(pn + 4) * 48 + ka];  // a2, a3
#pragma unroll
            for (int nt = 0; nt < 2; nt++) {
                int crow = cq * 16 + nt * 8 + c7;
                uint32_t b0 = BITS(x_s[cur][((2 * ks) * 66 + crow) * 4 + q3]);
                uint32_t b1 = BITS(x_s[cur][((2 * ks + 1) * 66 + crow) * 4 + q3]);
                mma8(acc[nt], BITS(pa.x), BITS(pa.y), BITS(pb.x), BITS(pb.y), b0, b1);
            }
        }
        if (tl < 24) { K2_STS(1 - cur, av, v0, v1); }   // write other buffer
        __syncthreads();
    }

    // fused epilogue: out = acc - wsum*cw  (acc rows are true k)
    const int k0 = mt * 16 + c7;
#pragma unroll
    for (int nt = 0; nt < 2; nt++) {
        int c = cb * 64 + cq * 16 + nt * 8 + 2 * q3;
#pragma unroll
        for (int half = 0; half < 2; half++) {
            int k = k0 + 8 * half;
            float2 cv = __ldg((const float2*)&cw[k * CDIM + c]);
            float ws = wsum_s[k];
            float2 o;
            o.x = acc[nt][2 * half]     - ws * cv.x;
            o.y = acc[nt][2 * half + 1] - ws * cv.y;
            *(float2*)&out[((size_t)b * KD + k) * CDIM + c] = o;
        }
    }
}

extern "C" void kernel_launch(void* const* d_in, const int* in_sizes, int n_in,
                              void* d_out, int out_size) {
    const float* x     = (const float*)d_in[0];
    const float* cw    = (const float*)d_in[1];
    const float* scale = (const float*)d_in[2];
    enc_k1<<<BDIM * CH1, 256>>>(x, cw, scale);
    enc_k2<<<BDIM * 8, 256>>>(x, cw, (float*)d_out);
}

// round 13
// speedup vs baseline: 1.0645x; 1.0645x over previous
#include <cuda_runtime.h>
#include <cstdint>

// Encoding: B=64, C=512, N=784, K=32. x:(B,C,N) f32; out:(B,K,C) f32.
// K1 (512 thr, 16 warps): logits mma tf32 + softmax -> A ([b][n][k]) + wsum.
//     warp = (k-tile 0..3, c-quarter 0..3); register-prefetched staging.
// K2 (round-10 proven): out = A^T x, 64-c blocks, double-buffered, fused epilogue.

#define CDIM 512
#define KD 32
#define NPIX 784
#define BDIM 64
#define CH1 9
#define TS 16
#define TILES1 49

__device__ float g_A[(size_t)BDIM * NPIX * KD];     // 6.4 MB, [b][n][k]
__device__ float g_wsum[BDIM * CH1 * KD];

__device__ __forceinline__ float rtf32(float v) {
    asm("cvt.rna.tf32.f32 %0, %1;" : "=f"(v) : "f"(v));
    return v;
}
__device__ __forceinline__ void mma8(float* d, uint32_t a0, uint32_t a1,
                                     uint32_t a2, uint32_t a3,
                                     uint32_t b0, uint32_t b1) {
    asm volatile(
        "mma.sync.aligned.m16n8k8.row.col.f32.tf32.tf32.f32 "
        "{%0,%1,%2,%3}, {%4,%5,%6,%7}, {%8,%9}, {%0,%1,%2,%3};"
        : "+f"(d[0]), "+f"(d[1]), "+f"(d[2]), "+f"(d[3])
        : "r"(a0), "r"(a1), "r"(a2), "r"(a3), "r"(b0), "r"(b1));
}
#define BITS(f) __float_as_uint(f)

// =========================== K1: logits + softmax (512 threads) ===========================
__global__ __launch_bounds__(512, 1) void enc_k1(const float* __restrict__ x,
                                                 const float* __restrict__ cw,
                                                 const float* __restrict__ scale) {
    const int b = blockIdx.x / CH1, ch = blockIdx.x % CH1;
    const int tile0 = ch * TILES1 / CH1, tile1 = (ch + 1) * TILES1 / CH1;
    const int t = threadIdx.x, w = t >> 5, l = t & 31;
    const int kt = w & 3, h = w >> 2;         // warp = (k-tile 0..3, c-quarter 0..3)

    __shared__ float x_s[TS * 516];
    __shared__ float xc_s[TS * 34];
    __shared__ float red_s[3 * 128 * 4];      // quarters 1..3 partial d4
    __shared__ float part_s[TS * 33];
    __shared__ float csq_s[KD], scl_s[KD];
    __shared__ float wsum_s[16][KD];

    if (t < KD) scl_s[t] = __ldg(&scale[t]);
    // csq: warps 0..7 (as round 10)
    if (w < 8) {
#pragma unroll
        for (int kk = 0; kk < 4; kk++) {
            int k = 4 * w + kk;
            float s = 0.f;
#pragma unroll
            for (int q = 0; q < 4; q++) {
                float4 v = __ldg((const float4*)&cw[k * CDIM + l * 16 + 4 * q]);
                float e0 = rtf32(v.x), e1 = rtf32(v.y), e2 = rtf32(v.z), e3 = rtf32(v.w);
                s += e0 * e0 + e1 * e1 + e2 * e2 + e3 * e3;
            }
#pragma unroll
            for (int o = 16; o; o >>= 1) s += __shfl_xor_sync(~0u, s, o);
            if (l == 0) csq_s[k] = s;
        }
    }

    // persistent codeword B-fragments: warp covers k=8kt..+7, c-quarter h (128 c)
    uint32_t cwf0[16], cwf1[16];
    const int crow = kt * 8 + (l >> 2), cp = l & 3;
#pragma unroll
    for (int s = 0; s < 16; s++) {
        int c = h * 128 + 8 * s + cp;
        cwf0[s] = BITS(rtf32(__ldg(&cw[crow * CDIM + c])));
        cwf1[s] = BITS(rtf32(__ldg(&cw[crow * CDIM + c + 4])));
    }

    float wsum_acc = 0.f;
    const float* xb = x + (size_t)b * CDIM * NPIX;
    const int nl = t & 15, cb32 = t >> 4;     // staging: row, c base (0..31)

    float buf[16];
#define LDREG(n0) _Pragma("unroll") \
    for (int i = 0; i < 16; i++) buf[i] = __ldg(&xb[(cb32 + 32 * i) * NPIX + (n0) + nl]);

    LDREG(tile0 * TS);
    for (int tile = tile0; tile < tile1; tile++) {
        const int n0 = tile * TS;
        __syncthreads();
        // commit prefetched tile (raw fp32; HMMA truncates) + xsq partial (exact)
        float xsqp = 0.f;
#pragma unroll
        for (int i = 0; i < 16; i++) {
            float v = buf[i];
            x_s[nl * 516 + cb32 + 32 * i] = v;
            xsqp = fmaf(v, v, xsqp);
        }
        part_s[nl * 33 + cb32] = xsqp;
        __syncthreads();
        if (tile + 1 < tile1) { LDREG(n0 + TS); }   // overlap next-tile DRAM latency

        // phase 1: xc = x . cw^T over c-quarter, 16 k-steps, 2 chains
        float dA[4] = {0.f, 0.f, 0.f, 0.f}, dB[4] = {0.f, 0.f, 0.f, 0.f};
        const int r0 = (l >> 2) * 516, r1 = r0 + 8 * 516;
#pragma unroll
        for (int s = 0; s < 16; s++) {
            int c = h * 128 + 8 * s + cp;
            uint32_t a0 = BITS(x_s[r0 + c]);
            uint32_t a1 = BITS(x_s[r1 + c]);
            uint32_t a2 = BITS(x_s[r0 + c + 4]);
            uint32_t a3 = BITS(x_s[r1 + c + 4]);
            mma8((s & 1) ? dB : dA, a0, a1, a2, a3, cwf0[s], cwf1[s]);
        }
        float d4[4];
#pragma unroll
        for (int i = 0; i < 4; i++) d4[i] = dA[i] + dB[i];
        if (h)
            *(float4*)&red_s[((h - 1) * 128 + kt * 32 + l) * 4] =
                make_float4(d4[0], d4[1], d4[2], d4[3]);
        __syncthreads();
        if (h == 0) {
#pragma unroll
            for (int q = 0; q < 3; q++) {
                float4 rr = *(const float4*)&red_s[(q * 128 + kt * 32 + l) * 4];
                d4[0] += rr.x; d4[1] += rr.y; d4[2] += rr.z; d4[3] += rr.w;
            }
            int rrow = l >> 2, cc = kt * 8 + 2 * (l & 3);
            *(float2*)&xc_s[rrow * 34 + cc] = make_float2(d4[0], d4[1]);
            *(float2*)&xc_s[(rrow + 8) * 34 + cc] = make_float2(d4[2], d4[3]);
        }
        __syncthreads();

        // softmax: warp w -> row n = w; lane = k; xsq via 32-partial shfl reduce
        {
            const int n = w;
            float xs = part_s[n * 33 + l];
#pragma unroll
            for (int o = 16; o; o >>= 1) xs += __shfl_xor_sync(~0u, xs, o);
            float xc = xc_s[n * 34 + l];
            float dd = scl_s[l] * (xs - 2.f * xc + csq_s[l]);
            float m = dd;
#pragma unroll
            for (int o = 16; o; o >>= 1) m = fmaxf(m, __shfl_xor_sync(~0u, m, o));
            float e = __expf(dd - m);
            float ss = e;
#pragma unroll
            for (int o = 16; o; o >>= 1) ss += __shfl_xor_sync(~0u, ss, o);
            float a = rtf32(__fdividef(e, ss));
            wsum_acc += a;
            g_A[((size_t)b * NPIX + n0 + n) * KD + l] = a;   // coalesced
        }
    }

    wsum_s[w][l] = wsum_acc;
    __syncthreads();
    if (t < KD) {
        float s = 0.f;
#pragma unroll
        for (int ww = 0; ww < 16; ww++) s += wsum_s[ww][t];
        g_wsum[(b * CH1 + ch) * KD + t] = s;
    }
}

// ==== K2: out = A^T x, 64-c blocks, double-buffered, fused epilogue (round-10) ====
// x_s: n-group j (=n/4, 0..7) major, stride 66 float4; (j, c, n%4) at (j*66+c)*4 + n%4.
__global__ __launch_bounds__(256) void enc_k2(const float* __restrict__ x,
                                              const float* __restrict__ cw,
                                              float* __restrict__ out) {
    const int b = blockIdx.x >> 3, cb = blockIdx.x & 7;   // cb: 64-c block
    const int t = threadIdx.x, w = t >> 5, l = t & 31;
    const int mt = w & 1, cq = w >> 1;   // warp = (k-half 16, c-quarter 16)

    __shared__ float A_s[2][32 * 40];      // [32n][32k], stride 40
    __shared__ float x_s[2][8 * 66 * 4];   // blocked, 2112 floats/buf
    __shared__ float wsum_s[KD];

    if (t < KD) {
        float s = 0.f;
#pragma unroll
        for (int ch = 0; ch < CH1; ch++) s += g_wsum[(b * CH1 + ch) * KD + t];
        wsum_s[t] = s;
    }

    float acc[2][4];
#pragma unroll
    for (int i = 0; i < 2; i++)
#pragma unroll
        for (int j = 0; j < 4; j++) acc[i][j] = 0.f;

    const float* xb = x + ((size_t)b * CDIM + cb * 64) * NPIX;
    const float* Ab = g_A + (size_t)b * NPIX * KD;
    const int ar = t >> 3, ak4 = t & 7;   // A staging: n row, k-float4
    const int xc_ = t >> 2, xj = t & 3;   // x staging: c row, n-group (and +4)

#define K2_LDG(n0, av, v0, v1) do { \
        av = ((n0) + ar < NPIX) \
            ? __ldg((const float4*)&Ab[(size_t)((n0) + ar) * KD + 4 * ak4]) \
            : make_float4(0.f, 0.f, 0.f, 0.f); \
        v0 = ((n0) + 4 * xj < NPIX) \
            ? __ldg((const float4*)&xb[(size_t)xc_ * NPIX + (n0) + 4 * xj]) \
            : make_float4(0.f, 0.f, 0.f, 0.f); \
        v1 = ((n0) + 4 * (xj + 4) < NPIX) \
            ? __ldg((const float4*)&xb[(size_t)xc_ * NPIX + (n0) + 4 * (xj + 4)]) \
            : make_float4(0.f, 0.f, 0.f, 0.f); \
    } while (0)

#define K2_STS(bi, av, v0, v1) do { \
        *(float4*)&A_s[bi][ar * 40 + 4 * ak4] = av; \
        *(float4*)&x_s[bi][(xj * 66 + xc_) * 4] = v0; \
        *(float4*)&x_s[bi][((xj + 4) * 66 + xc_) * 4] = v1; \
    } while (0)

    {   // prologue: stage tile 0 into buffer 0
        float4 av, v0, v1;
        K2_LDG(0, av, v0, v1);
        K2_STS(0, av, v0, v1);
    }
    __syncthreads();

    const int q3 = l & 3, c7 = l >> 2;

    for (int tl = 0; tl < 25; tl++) {
        const int cur = tl & 1;
        float4 av, v0, v1;
        if (tl < 24) { K2_LDG((tl + 1) * 32, av, v0, v1); }   // overlap with mma

#pragma unroll
        for (int ks = 0; ks < 4; ks++) {
            int pn = 8 * ks + q3;
            uint32_t a0 = BITS(A_s[cur][pn * 40 + mt * 16 + c7]);
            uint32_t a1 = BITS(A_s[cur][pn * 40 + mt * 16 + c7 + 8]);
            uint32_t a2 = BITS(A_s[cur][(pn + 4) * 40 + mt * 16 + c7]);
            uint32_t a3 = BITS(A_s[cur][(pn + 4) * 40 + mt * 16 + c7 + 8]);
#pragma unroll
            for (int nt = 0; nt < 2; nt++) {
                int crow = cq * 16 + nt * 8 + c7;
                uint32_t b0 = BITS(x_s[cur][((2 * ks) * 66 + crow) * 4 + q3]);
                uint32_t b1 = BITS(x_s[cur][((2 * ks + 1) * 66 + crow) * 4 + q3]);
                mma8(acc[nt], a0, a1, a2, a3, b0, b1);
            }
        }
        if (tl < 24) { K2_STS(1 - cur, av, v0, v1); }   // write other buffer
        __syncthreads();
    }

    // fused epilogue: out = acc - wsum*cw
    const int k0 = mt * 16 + c7;
#pragma unroll
    for (int nt = 0; nt < 2; nt++) {
        int c = cb * 64 + cq * 16 + nt * 8 + 2 * q3;
#pragma unroll
        for (int half = 0; half < 2; half++) {
            int k = k0 + 8 * half;
            float2 cv = __ldg((const float2*)&cw[k * CDIM + c]);
            float ws = wsum_s[k];
            float2 o;
            o.x = acc[nt][2 * half]     - ws * cv.x;
            o.y = acc[nt][2 * half + 1] - ws * cv.y;
            *(float2*)&out[((size_t)b * KD + k) * CDIM + c] = o;
        }
    }
}

extern "C" void kernel_launch(void* const* d_in, const int* in_sizes, int n_in,
                              void* d_out, int out_size) {
    const float* x     = (const float*)d_in[0];
    const float* cw    = (const float*)d_in[1];
    const float* scale = (const float*)d_in[2];
    enc_k1<<<BDIM * CH1, 512>>>(x, cw, scale);
    enc_k2<<<BDIM * 8, 256>>>(x, cw, (float*)d_out);
}

// round 14
// speedup vs baseline: 1.0694x; 1.0047x over previous
#include <cuda_runtime.h>
#include <cstdint>

// Encoding: B=64, C=512, N=784, K=32. x:(B,C,N) f32; out:(B,K,C) f32.
// K1 (round-10 proven): logits mma tf32 + softmax -> A ([b][n][k]) + wsum.
// K2: out = A^T x, 64-c blocks, 4-buffer cp.async.16B pipeline (depth 3), fused epilogue.

#define CDIM 512
#define KD 32
#define NPIX 784
#define BDIM 64
#define CH1 9
#define TS 16
#define TILES1 49

__device__ float g_A[(size_t)BDIM * NPIX * KD];     // 6.4 MB, [b][n][k]
__device__ float g_wsum[BDIM * CH1 * KD];

__device__ __forceinline__ float rtf32(float v) {
    asm("cvt.rna.tf32.f32 %0, %1;" : "=f"(v) : "f"(v));
    return v;
}
__device__ __forceinline__ void mma8(float* d, uint32_t a0, uint32_t a1,
                                     uint32_t a2, uint32_t a3,
                                     uint32_t b0, uint32_t b1) {
    asm volatile(
        "mma.sync.aligned.m16n8k8.row.col.f32.tf32.tf32.f32 "
        "{%0,%1,%2,%3}, {%4,%5,%6,%7}, {%8,%9}, {%0,%1,%2,%3};"
        : "+f"(d[0]), "+f"(d[1]), "+f"(d[2]), "+f"(d[3])
        : "r"(a0), "r"(a1), "r"(a2), "r"(a3), "r"(b0), "r"(b1));
}
__device__ __forceinline__ uint32_t smem_u32(const void* p) {
    uint32_t a;
    asm("{ .reg .u64 t; cvta.to.shared.u64 t, %1; cvt.u32.u64 %0, t; }" : "=r"(a) : "l"(p));
    return a;
}
__device__ __forceinline__ void cpa16(uint32_t sa, const void* g, int szbytes) {
    asm volatile("cp.async.ca.shared.global [%0], [%1], 16, %2;"
                 :: "r"(sa), "l"(g), "r"(szbytes));
}
#define CPA_COMMIT() asm volatile("cp.async.commit_group;" ::: "memory")
#define CPA_WAIT2()  asm volatile("cp.async.wait_group 2;" ::: "memory")
#define BITS(f) __float_as_uint(f)

// =========================== K1: logits + softmax (round-10) ===========================
__global__ __launch_bounds__(256) void enc_k1(const float* __restrict__ x,
                                              const float* __restrict__ cw,
                                              const float* __restrict__ scale) {
    const int b = blockIdx.x / CH1, ch = blockIdx.x % CH1;
    const int tile0 = ch * TILES1 / CH1, tile1 = (ch + 1) * TILES1 / CH1;
    const int t = threadIdx.x, w = t >> 5, l = t & 31;
    const int kt = w & 3, h = w >> 2;         // warp = (k-tile, c-half)

    __shared__ float x_s[TS * 516];
    __shared__ float xc_s[TS * 34];
    __shared__ float red_s[4 * 32 * 4];
    __shared__ float part_s[TS * 17];
    __shared__ float csq_s[KD], scl_s[KD];
    __shared__ float wsum_s[8][KD];

    if (t < KD) scl_s[t] = __ldg(&scale[t]);
#pragma unroll
    for (int kk = 0; kk < 4; kk++) {
        int k = 4 * w + kk;
        float s = 0.f;
#pragma unroll
        for (int q = 0; q < 4; q++) {
            float4 v = __ldg((const float4*)&cw[k * CDIM + l * 16 + 4 * q]);
            float e0 = rtf32(v.x), e1 = rtf32(v.y), e2 = rtf32(v.z), e3 = rtf32(v.w);
            s += e0 * e0 + e1 * e1 + e2 * e2 + e3 * e3;
        }
#pragma unroll
        for (int o = 16; o; o >>= 1) s += __shfl_xor_sync(~0u, s, o);
        if (l == 0) csq_s[k] = s;
    }

    // persistent codeword B-fragments (tf32): warp covers k=8kt..+7, c-half h
    uint32_t cwf0[32], cwf1[32];
    const int crow = kt * 8 + (l >> 2), cp = l & 3;
#pragma unroll
    for (int s = 0; s < 32; s++) {
        int c = h * 256 + 8 * s + cp;
        cwf0[s] = BITS(rtf32(__ldg(&cw[crow * CDIM + c])));
        cwf1[s] = BITS(rtf32(__ldg(&cw[crow * CDIM + c + 4])));
    }

    float wsum_acc = 0.f;
    const float* xb = x + (size_t)b * CDIM * NPIX;
    const int nl = t & 15, cb16 = t >> 4;

    float buf[32];
#define LDREG(n0) _Pragma("unroll") \
    for (int i = 0; i < 32; i++) buf[i] = __ldg(&xb[(cb16 + 16 * i) * NPIX + (n0) + nl]);

    LDREG(tile0 * TS);
    for (int tile = tile0; tile < tile1; tile++) {
        const int n0 = tile * TS;
        __syncthreads();
        // commit prefetched tile (tf32) + xsq partial
        float xsqp = 0.f;
#pragma unroll
        for (int i = 0; i < 32; i++) {
            float v = rtf32(buf[i]);
            x_s[nl * 516 + cb16 + 16 * i] = v;
            xsqp = fmaf(v, v, xsqp);
        }
        part_s[nl * 17 + cb16] = xsqp;
        __syncthreads();
        if (tile + 1 < tile1) { LDREG(n0 + TS); }   // overlap next-tile DRAM latency

        // phase 1: xc = x . cw^T, 32 k-steps, 2 accumulation chains
        float dA[4] = {0.f, 0.f, 0.f, 0.f}, dB[4] = {0.f, 0.f, 0.f, 0.f};
        const int r0 = (l >> 2) * 516, r1 = r0 + 8 * 516;
#pragma unroll
        for (int s = 0; s < 32; s++) {
            int c = h * 256 + 8 * s + cp;
            uint32_t a0 = BITS(x_s[r0 + c]);
            uint32_t a1 = BITS(x_s[r1 + c]);
            uint32_t a2 = BITS(x_s[r0 + c + 4]);
            uint32_t a3 = BITS(x_s[r1 + c + 4]);
            mma8((s & 1) ? dB : dA, a0, a1, a2, a3, cwf0[s], cwf1[s]);
        }
        float d4[4];
#pragma unroll
        for (int i = 0; i < 4; i++) d4[i] = dA[i] + dB[i];
        if (h == 1)
            *(float4*)&red_s[(kt * 32 + l) * 4] = make_float4(d4[0], d4[1], d4[2], d4[3]);
        __syncthreads();
        if (h == 0) {
            float4 rr = *(const float4*)&red_s[(kt * 32 + l) * 4];
            d4[0] += rr.x; d4[1] += rr.y; d4[2] += rr.z; d4[3] += rr.w;
            int rrow = l >> 2, cc = kt * 8 + 2 * (l & 3);
            *(float2*)&xc_s[rrow * 34 + cc] = make_float2(d4[0], d4[1]);
            *(float2*)&xc_s[(rrow + 8) * 34 + cc] = make_float2(d4[2], d4[3]);
        }
        __syncthreads();

        // softmax: warp w rows {w, w+8}, lane = k
#pragma unroll
        for (int r = 0; r < 2; r++) {
            int n = w + 8 * r;
            float xs = 0.f;
#pragma unroll
            for (int q = 0; q < 16; q++) xs += part_s[n * 17 + q];
            float xc = xc_s[n * 34 + l];
            float dd = scl_s[l] * (xs - 2.f * xc + csq_s[l]);
            float m = dd;
#pragma unroll
            for (int o = 16; o; o >>= 1) m = fmaxf(m, __shfl_xor_sync(~0u, m, o));
            float e = __expf(dd - m);
            float ss = e;
#pragma unroll
            for (int o = 16; o; o >>= 1) ss += __shfl_xor_sync(~0u, ss, o);
            float a = rtf32(__fdividef(e, ss));
            wsum_acc += a;
            g_A[((size_t)b * NPIX + n0 + n) * KD + l] = a;   // coalesced
        }
    }

    wsum_s[w][l] = wsum_acc;
    __syncthreads();
    if (t < KD) {
        float s = 0.f;
#pragma unroll
        for (int ww = 0; ww < 8; ww++) s += wsum_s[ww][t];
        g_wsum[(b * CH1 + ch) * KD + t] = s;
    }
}

// ==== K2: out = A^T x, 64-c blocks, cp.async 4-buffer pipeline, fused epilogue ====
// Layouts identical to round-10: A_s [32n][32k] stride 40; x_s n-group blocked stride 66 f4.
__global__ __launch_bounds__(256) void enc_k2(const float* __restrict__ x,
                                              const float* __restrict__ cw,
                                              float* __restrict__ out) {
    const int b = blockIdx.x >> 3, cb = blockIdx.x & 7;   // cb: 64-c block
    const int t = threadIdx.x, w = t >> 5, l = t & 31;
    const int mt = w & 1, cq = w >> 1;   // warp = (k-half 16, c-quarter 16)

    __shared__ float A_s[4][32 * 40];      // 1280 floats per buf
    __shared__ float x_s[4][8 * 66 * 4];   // 2112 floats per buf
    __shared__ float wsum_s[KD];

    if (t < KD) {
        float s = 0.f;
#pragma unroll
        for (int ch = 0; ch < CH1; ch++) s += g_wsum[(b * CH1 + ch) * KD + t];
        wsum_s[t] = s;
    }

    float acc[2][4];
#pragma unroll
    for (int i = 0; i < 2; i++)
#pragma unroll
        for (int j = 0; j < 4; j++) acc[i][j] = 0.f;

    const float* xb = x + ((size_t)b * CDIM + cb * 64) * NPIX;
    const float* Ab = g_A + (size_t)b * NPIX * KD;
    const int ar = t >> 3, ak4 = t & 7;   // A staging: n row, k-float4
    const int xc_ = t >> 2, xj = t & 3;   // x staging: c row, n-group (and +4)
    const uint32_t Abase = smem_u32(A_s), Xbase = smem_u32(x_s);

    // one 3x16B cp.async group per tile; bounds via src_size (0 -> zero-fill)
#define K2_ISSUE(tl_) do { \
        int n0_ = (tl_) * 32, bi_ = (tl_) & 3; \
        int an_ = n0_ + ar; \
        cpa16(Abase + 4u * (bi_ * 1280 + ar * 40 + 4 * ak4), \
              Ab + (size_t)(an_ < NPIX ? an_ : 0) * KD + 4 * ak4, \
              an_ < NPIX ? 16 : 0); \
        int x0_ = n0_ + 4 * xj; \
        cpa16(Xbase + 4u * (bi_ * 2112 + (xj * 66 + xc_) * 4), \
              xb + (size_t)xc_ * NPIX + (x0_ < NPIX ? x0_ : 0), \
              x0_ < NPIX ? 16 : 0); \
        int x1_ = n0_ + 4 * (xj + 4); \
        cpa16(Xbase + 4u * (bi_ * 2112 + ((xj + 4) * 66 + xc_) * 4), \
              xb + (size_t)xc_ * NPIX + (x1_ < NPIX ? x1_ : 0), \
              x1_ < NPIX ? 16 : 0); \
        CPA_COMMIT(); \
    } while (0)

    K2_ISSUE(0); K2_ISSUE(1); K2_ISSUE(2);   // 3-deep prologue

    const int q3 = l & 3, c7 = l >> 2;

    for (int tl = 0; tl < 25; tl++) {
        CPA_WAIT2();           // tile tl landed (2 younger groups may be in flight)
        __syncthreads();       // publish; also fences buffer (tl-1)&3 reads from iter tl-1
        if (tl + 3 < 25) { K2_ISSUE(tl + 3); } else { CPA_COMMIT(); }  // keep group count exact

        const int cur = tl & 3;
#pragma unroll
        for (int ks = 0; ks < 4; ks++) {
            int pn = 8 * ks + q3;
            uint32_t a0 = BITS(A_s[cur][pn * 40 + mt * 16 + c7]);
            uint32_t a1 = BITS(A_s[cur][pn * 40 + mt * 16 + c7 + 8]);
            uint32_t a2 = BITS(A_s[cur][(pn + 4) * 40 + mt * 16 + c7]);
            uint32_t a3 = BITS(A_s[cur][(pn + 4) * 40 + mt * 16 + c7 + 8]);
#pragma unroll
            for (int nt = 0; nt < 2; nt++) {
                int crow = cq * 16 + nt * 8 + c7;
                uint32_t b0 = BITS(x_s[cur][((2 * ks) * 66 + crow) * 4 + q3]);
                uint32_t b1 = BITS(x_s[cur][((2 * ks + 1) * 66 + crow) * 4 + q3]);
                mma8(acc[nt], a0, a1, a2, a3, b0, b1);
            }
        }
    }

    // fused epilogue: out = acc - wsum*cw
    const int k0 = mt * 16 + c7;
#pragma unroll
    for (int nt = 0; nt < 2; nt++) {
        int c = cb * 64 + cq * 16 + nt * 8 + 2 * q3;
#pragma unroll
        for (int half = 0; half < 2; half++) {
            int k = k0 + 8 * half;
            float2 cv = __ldg((const float2*)&cw[k * CDIM + c]);
            float ws = wsum_s[k];
            float2 o;
            o.x = acc[nt][2 * half]     - ws * cv.x;
            o.y = acc[nt][2 * half + 1] - ws * cv.y;
            *(float2*)&out[((size_t)b * KD + k) * CDIM + c] = o;
        }
    }
}

extern "C" void kernel_launch(void* const* d_in, const int* in_sizes, int n_in,
                              void* d_out, int out_size) {
    const float* x     = (const float*)d_in[0];
    const float* cw    = (const float*)d_in[1];
    const float* scale = (const float*)d_in[2];
    enc_k1<<<BDIM * CH1, 256>>>(x, cw, scale);
    enc_k2<<<BDIM * 8, 256>>>(x, cw, (float*)d_out);
}